// round 4
// baseline (speedup 1.0000x reference)
#include <cuda_runtime.h>
#include <cstdint>

// LinearTPReadOut: out[n] = w_tp/sqrt(3) * (1/128) * sum_i A_i(n)*B_i(n)
//   A_i(n) = sum_u x[n, 128+3u+i] * w_lin[u,0],  B_i with w_lin[u,1]
// x: (N,1152) f32, w_lin: (128,2) f32, w_tp: (1,) f32, out: (N,) f32
//
// Octet-per-row: 8 lanes cooperate on one row, 4 rows per warp in parallel.
// Lane (group-lane gl) loads float4 indices gl+8k, k=0..11 of the 384-float
// span -- 12 LDG.128 front-batched = 1536B in flight per warp (latency hidden
// by MLP, not occupancy). Channel rotation: position e = 4gl+32k+c has
// channel i = ((2k+c)%3 + gl%3)%3; accumulate into rot[(2k+c)%3]
// (compile-time), fix up with SELs. Width-8 butterfly reduction:
// 12 shfl per 4 rows. Weights from expanded smem arrays (broadcast LDS.128).

#define ROW_STRIDE_F   1152
#define COL_OFF        128
#define ITERS          4       // 4 rows/iter * 4 iters = 16 rows per warp

#define LDS128(r0, r1, r2, r3, addr)                                  \
    asm volatile("ld.shared.v4.f32 {%0,%1,%2,%3}, [%4];"              \
                 : "=f"(r0), "=f"(r1), "=f"(r2), "=f"(r3) : "r"(addr))

__global__ __launch_bounds__(256)
void lintp_kernel(const float* __restrict__ x,
                  const float* __restrict__ w_lin,
                  const float* __restrict__ w_tp,
                  float* __restrict__ out, int n)
{
    __shared__ float wexp[2][384];   // [0][e]=w0[e/3], [1][e]=w1[e/3]

    const int tid = threadIdx.x;
    for (int e = tid; e < 384; e += 256) {
        const float2 p = *reinterpret_cast<const float2*>(w_lin + 2 * (e / 3));
        wexp[0][e] = p.x;
        wexp[1][e] = p.y;
    }
    __syncthreads();

    const int lane = tid & 31;
    const int gl   = lane & 7;     // lane within octet
    const int g    = lane >> 3;    // octet (row) index within warp
    const int warpGlobal = (blockIdx.x * blockDim.x + tid) >> 5;

    int row0 = warpGlobal * (4 * ITERS);
    if (row0 >= n) return;

    const uint32_t wbaseA =
        (uint32_t)__cvta_generic_to_shared(&wexp[0][0]) + (uint32_t)gl * 16u;
    const uint32_t wbaseB = wbaseA + 1536u;
    const float scale = __ldg(w_tp) * 0.57735026918962576451f * (1.0f / 128.0f);
    const int s = gl % 3;          // lane channel shift (= (4*gl)%3)

    for (int it = 0; it < ITERS; it++, row0 += 4) {
        const int row  = row0 + g;
        const int rowc = row < n ? row : n - 1;   // clamp: keep all lanes live
        const float4* xp = reinterpret_cast<const float4*>(
            x + (size_t)rowc * ROW_STRIDE_F + COL_OFF) + gl;

        float4 v[12];
        #pragma unroll
        for (int k = 0; k < 12; k++) v[k] = xp[8 * k];

        float rA0 = 0.f, rA1 = 0.f, rA2 = 0.f;
        float rB0 = 0.f, rB1 = 0.f, rB2 = 0.f;

        #pragma unroll
        for (int k = 0; k < 12; k++) {
            float a0, a1, a2, a3, b0, b1, b2, b3;
            LDS128(a0, a1, a2, a3, wbaseA + 128u * (uint32_t)k);
            LDS128(b0, b1, b2, b3, wbaseB + 128u * (uint32_t)k);

            #define ACC(VV, AA, BB, J)                                         \
                do {                                                           \
                    if ((J) == 0)      { rA0 = fmaf(VV, AA, rA0); rB0 = fmaf(VV, BB, rB0); } \
                    else if ((J) == 1) { rA1 = fmaf(VV, AA, rA1); rB1 = fmaf(VV, BB, rB1); } \
                    else               { rA2 = fmaf(VV, AA, rA2); rB2 = fmaf(VV, BB, rB2); } \
                } while (0)

            ACC(v[k].x, a0, b0, (2 * k + 0) % 3);
            ACC(v[k].y, a1, b1, (2 * k + 1) % 3);
            ACC(v[k].z, a2, b2, (2 * k + 2) % 3);
            ACC(v[k].w, a3, b3, (2 * k + 3) % 3);
            #undef ACC
        }

        // un-rotate B partials to absolute channels: B_i <- rot[(i - s) mod 3]
        float b_0 = (s == 0) ? rB0 : ((s == 1) ? rB2 : rB1);
        float b_1 = (s == 0) ? rB1 : ((s == 1) ? rB0 : rB2);
        float b_2 = (s == 0) ? rB2 : ((s == 1) ? rB1 : rB0);

        // butterfly-reduce within octet (masks 4,2,1 stay inside 8 lanes)
        #pragma unroll
        for (int m = 4; m > 0; m >>= 1) {
            b_0 += __shfl_xor_sync(0xffffffffu, b_0, m);
            b_1 += __shfl_xor_sync(0xffffffffu, b_1, m);
            b_2 += __shfl_xor_sync(0xffffffffu, b_2, m);
        }

        // per-lane partial of sum_i A_i*B_i: pair rA[j] (channel (j+s)%3)
        // with full B of the same channel
        const float Bs0 = (s == 0) ? b_0 : ((s == 1) ? b_1 : b_2);
        const float Bs1 = (s == 0) ? b_1 : ((s == 1) ? b_2 : b_0);
        const float Bs2 = (s == 0) ? b_2 : ((s == 1) ? b_0 : b_1);
        float p = rA0 * Bs0;
        p = fmaf(rA1, Bs1, p);
        p = fmaf(rA2, Bs2, p);

        #pragma unroll
        for (int m = 4; m > 0; m >>= 1)
            p += __shfl_xor_sync(0xffffffffu, p, m);

        if (gl == 0 && row < n)
            out[row] = scale * p;
    }
}

extern "C" void kernel_launch(void* const* d_in, const int* in_sizes, int n_in,
                              void* d_out, int out_size)
{
    const float* x     = (const float*)d_in[0];
    const float* w_lin = (const float*)d_in[1];
    const float* w_tp  = (const float*)d_in[2];
    float* out = (float*)d_out;

    const int n = in_sizes[0] / ROW_STRIDE_F;          // 200000
    const int rowsPerBlock = 8 * 4 * ITERS;            // 8 warps * 16 rows
    const int blocks = (n + rowsPerBlock - 1) / rowsPerBlock;
    lintp_kernel<<<blocks, 256>>>(x, w_lin, w_tp, out, n);
}